// round 3
// baseline (speedup 1.0000x reference)
#include <cuda_runtime.h>
#include <stdint.h>

#define NBLK 1184   // 8 blocks/SM on 148 SMs (152 on GB300 -> still one wave)
#define NTHR 256
#define NCOL 16

// Per-block partials — fully overwritten every launch (graph-safe).
__device__ float g_psum[NBLK][NCOL];
__device__ float g_pcnt[NBLK][NCOL];
__device__ __align__(16) float g_mean[NCOL];
// Monotonic barrier ticket counter; generation math is wrap-safe and
// replay-safe (advances by exactly NBLK per barrier episode).
__device__ unsigned int g_arrive = 0;

__device__ __forceinline__ bool is_nan_bits(float v) {
    return (__float_as_uint(v) & 0x7fffffffu) > 0x7f800000u;
}

__device__ __forceinline__ void grid_barrier() {
    __syncthreads();
    if (threadIdx.x == 0) {
        __threadfence();
        unsigned int ticket = atomicAdd(&g_arrive, 1u);
        unsigned int target = ticket - (ticket % NBLK) + NBLK;
        while ((int)(atomicAdd(&g_arrive, 0u) - target) < 0) __nanosleep(64);
        __threadfence();
    }
    __syncthreads();
}

__device__ __forceinline__ void acc4(float4 v,
                                     float& sx, float& sy, float& sz, float& sw,
                                     float& cx, float& cy, float& cz, float& cw) {
    if (!is_nan_bits(v.x)) { sx += v.x; cx += 1.f; }
    if (!is_nan_bits(v.y)) { sy += v.y; cy += 1.f; }
    if (!is_nan_bits(v.z)) { sz += v.z; cz += 1.f; }
    if (!is_nan_bits(v.w)) { sw += v.w; cw += 1.f; }
}

__global__ void __launch_bounds__(NTHR, 8) fused_k(const float4* __restrict__ in,
                                                   float4* __restrict__ out, int n4) {
    const int tid    = blockIdx.x * NTHR + threadIdx.x;
    const int stride = NBLK * NTHR;          // multiple of 4 -> column group constant
    // ---------------- Phase A: reduce (streams input into L2) ----------------
    {
        float sx = 0.f, sy = 0.f, sz = 0.f, sw = 0.f;
        float cx = 0.f, cy = 0.f, cz = 0.f, cw = 0.f;
        int i = tid;
        for (; i + 3 * stride < n4; i += 4 * stride) {
            float4 v0 = in[i];
            float4 v1 = in[i + stride];
            float4 v2 = in[i + 2 * stride];
            float4 v3 = in[i + 3 * stride];
            acc4(v0, sx, sy, sz, sw, cx, cy, cz, cw);
            acc4(v1, sx, sy, sz, sw, cx, cy, cz, cw);
            acc4(v2, sx, sy, sz, sw, cx, cy, cz, cw);
            acc4(v3, sx, sy, sz, sw, cx, cy, cz, cw);
        }
        for (; i < n4; i += stride) {
            acc4(in[i], sx, sy, sz, sw, cx, cy, cz, cw);
        }
        #pragma unroll
        for (int d = 4; d < 32; d <<= 1) {
            sx += __shfl_xor_sync(0xffffffffu, sx, d);
            sy += __shfl_xor_sync(0xffffffffu, sy, d);
            sz += __shfl_xor_sync(0xffffffffu, sz, d);
            sw += __shfl_xor_sync(0xffffffffu, sw, d);
            cx += __shfl_xor_sync(0xffffffffu, cx, d);
            cy += __shfl_xor_sync(0xffffffffu, cy, d);
            cz += __shfl_xor_sync(0xffffffffu, cz, d);
            cw += __shfl_xor_sync(0xffffffffu, cw, d);
        }
        __shared__ float sh[2 * NCOL];
        if (threadIdx.x < 2 * NCOL) sh[threadIdx.x] = 0.f;
        __syncthreads();
        int lane = threadIdx.x & 31;
        if (lane < 4) {
            int c0 = lane * 4;
            atomicAdd(&sh[c0 + 0], sx);
            atomicAdd(&sh[c0 + 1], sy);
            atomicAdd(&sh[c0 + 2], sz);
            atomicAdd(&sh[c0 + 3], sw);
            atomicAdd(&sh[NCOL + c0 + 0], cx);
            atomicAdd(&sh[NCOL + c0 + 1], cy);
            atomicAdd(&sh[NCOL + c0 + 2], cz);
            atomicAdd(&sh[NCOL + c0 + 3], cw);
        }
        __syncthreads();
        if (threadIdx.x < NCOL) {
            g_psum[blockIdx.x][threadIdx.x] = sh[threadIdx.x];
            g_pcnt[blockIdx.x][threadIdx.x] = sh[NCOL + threadIdx.x];
        }
    }
    grid_barrier();
    // ---------------- Phase B: block 0 folds partials -> g_mean ----------------
    if (blockIdx.x == 0) {
        __shared__ float fs[NCOL], fc[NCOL];
        int t = threadIdx.x;
        if (t < NCOL) { fs[t] = 0.f; fc[t] = 0.f; }
        __syncthreads();
        int col = t & (NCOL - 1);
        int grp = t >> 4;                    // 16 groups of 16 threads
        float s = 0.f, c = 0.f;
        for (int b = grp; b < NBLK; b += 16) {
            s += g_psum[b][col];
            c += g_pcnt[b][col];
        }
        atomicAdd(&fs[col], s);
        atomicAdd(&fc[col], c);
        __syncthreads();
        if (t < NCOL) g_mean[t] = fs[t] / fmaxf(fc[t], 1.0f);
        __threadfence();
    }
    grid_barrier();
    // ---------------- Phase C: fill (reads should hit L2) ----------------
    {
        int i0 = n4 - 1 - tid;
        if (i0 < 0) return;
        float4 m;
        {   // bypass L1 for the freshly-written means
            const float* gm = g_mean + (i0 & 3) * 4;
            m.x = __ldcg(gm + 0); m.y = __ldcg(gm + 1);
            m.z = __ldcg(gm + 2); m.w = __ldcg(gm + 3);
        }
        int i = i0;
        for (; i - 3 * stride >= 0; i -= 4 * stride) {
            float4 v0 = __ldcg(&in[i]);
            float4 v1 = __ldcg(&in[i - stride]);
            float4 v2 = __ldcg(&in[i - 2 * stride]);
            float4 v3 = __ldcg(&in[i - 3 * stride]);
            if (is_nan_bits(v0.x)) v0.x = m.x;
            if (is_nan_bits(v0.y)) v0.y = m.y;
            if (is_nan_bits(v0.z)) v0.z = m.z;
            if (is_nan_bits(v0.w)) v0.w = m.w;
            if (is_nan_bits(v1.x)) v1.x = m.x;
            if (is_nan_bits(v1.y)) v1.y = m.y;
            if (is_nan_bits(v1.z)) v1.z = m.z;
            if (is_nan_bits(v1.w)) v1.w = m.w;
            if (is_nan_bits(v2.x)) v2.x = m.x;
            if (is_nan_bits(v2.y)) v2.y = m.y;
            if (is_nan_bits(v2.z)) v2.z = m.z;
            if (is_nan_bits(v2.w)) v2.w = m.w;
            if (is_nan_bits(v3.x)) v3.x = m.x;
            if (is_nan_bits(v3.y)) v3.y = m.y;
            if (is_nan_bits(v3.z)) v3.z = m.z;
            if (is_nan_bits(v3.w)) v3.w = m.w;
            __stcs(&out[i], v0);
            __stcs(&out[i - stride], v1);
            __stcs(&out[i - 2 * stride], v2);
            __stcs(&out[i - 3 * stride], v3);
        }
        for (; i >= 0; i -= stride) {
            float4 v = __ldcg(&in[i]);
            if (is_nan_bits(v.x)) v.x = m.x;
            if (is_nan_bits(v.y)) v.y = m.y;
            if (is_nan_bits(v.z)) v.z = m.z;
            if (is_nan_bits(v.w)) v.w = m.w;
            __stcs(&out[i], v);
        }
    }
}

extern "C" void kernel_launch(void* const* d_in, const int* in_sizes, int n_in,
                              void* d_out, int out_size) {
    const float4* in4 = (const float4*)d_in[0];
    float4* out4 = (float4*)d_out;
    int n4 = in_sizes[0] / 4;                // B*T*C with C=16 -> divisible by 4
    fused_k<<<NBLK, NTHR>>>(in4, out4, n4);
}